// round 16
// baseline (speedup 1.0000x reference)
#include <cuda_runtime.h>
#include <cuda_fp16.h>
#include <math.h>

#define TT   30
#define BB   32
#define VV   32
#define FF   128
#define LL   256
#define LFF  64
#define HH   8
#define DHH  16
#define HISTN 10
#define MROWS (TT*BB*VV)   // 30720

// ---- mma helpers ----
__device__ __forceinline__ unsigned tf32u(float x) {
    unsigned u; asm("cvt.rna.tf32.f32 %0,%1;" : "=r"(u) : "f"(x)); return u;
}
__device__ __forceinline__ void mma_tf32(float* c, const unsigned* a, unsigned b0, unsigned b1) {
    asm volatile("mma.sync.aligned.m16n8k8.row.col.f32.tf32.tf32.f32 "
        "{%0,%1,%2,%3},{%4,%5,%6,%7},{%8,%9},{%0,%1,%2,%3};"
        : "+f"(c[0]), "+f"(c[1]), "+f"(c[2]), "+f"(c[3])
        : "r"(a[0]), "r"(a[1]), "r"(a[2]), "r"(a[3]), "r"(b0), "r"(b1));
}
__device__ __forceinline__ void mma_f16(float* c, const unsigned* a, unsigned b0, unsigned b1) {
    asm volatile("mma.sync.aligned.m16n8k16.row.col.f32.f16.f16.f32 "
        "{%0,%1,%2,%3},{%4,%5,%6,%7},{%8,%9},{%0,%1,%2,%3};"
        : "+f"(c[0]), "+f"(c[1]), "+f"(c[2]), "+f"(c[3])
        : "r"(a[0]), "r"(a[1]), "r"(a[2]), "r"(a[3]), "r"(b0), "r"(b1));
}
__device__ __forceinline__ unsigned h2ex2(unsigned h) {
    unsigned r; asm("ex2.approx.f16x2 %0,%1;" : "=r"(r) : "r"(h)); return r;
}
__device__ __forceinline__ unsigned packh2(float a, float b) {
    __half2 h = __floats2half2_rn(a, b); return *(unsigned*)&h;
}

// ---------------- scratch ----------------
__device__ float g_Kproj[BB*LL*FF];
__device__ float g_LV[BB*LL*FF];
__device__ unsigned char g_mask[BB*LL];
__device__ float g_q[MROWS*FF];
__device__ float g_r[MROWS*FF];
__device__ float g_pre[MROWS*FF];

// ---------------- lane projection ----------------
template<bool LOGSIG>
__global__ __launch_bounds__(256) void lane_proj_kernel(
    const float* __restrict__ lanes, const float* __restrict__ W,
    const float* __restrict__ bias, float* __restrict__ out)
{
    __shared__ float Wsh[LFF][FF + 1];
    __shared__ float lsh[32][LFF];
    __shared__ float bsh[FF];
    int tid = threadIdx.x;
    int row0 = blockIdx.x * 32;

    #pragma unroll
    for (int i = 0; i < 32; i++) {
        int idx = tid + i * 256;
        int f = idx >> 6, j = idx & 63;
        Wsh[j][f] = W[idx];
    }
    if (tid < FF) bsh[tid] = bias[tid];
    #pragma unroll
    for (int i = 0; i < 2; i++) {
        int idx = tid + i * 256;
        int r = idx >> 4;
        int c = (idx & 15) * 4;
        *(float4*)&lsh[r][c] = *(const float4*)(lanes + (size_t)(row0 + r) * LFF + c);
    }
    __syncthreads();

    int f = tid & 127;
    for (int r = tid >> 7; r < 32; r += 2) {
        float acc = bsh[f];
        #pragma unroll
        for (int j = 0; j < LFF; j++) acc += lsh[r][j] * Wsh[j][f];
        if (LOGSIG) {
            acc = (acc >= 0.f) ? -__logf(1.f + __expf(-acc))
                               : acc - __logf(1.f + __expf(acc));
        }
        out[(size_t)(row0 + r) * FF + f] = acc;
    }
}

// ---------------- mask ----------------
__global__ void mask_kernel(const unsigned char* __restrict__ m)
{
    int tid = threadIdx.x;
    const unsigned int* w = (const unsigned int*)m;
    bool okI = true, okF = true;
    for (int j = tid; j < (HISTN * BB * LL) / 4; j += 256) {
        unsigned int x = w[j];
        if (x > 1u) okI = false;
        if (x != 0u && x != 0x3F800000u) okF = false;
    }
    okI = __syncthreads_and((int)okI) != 0;
    okF = __syncthreads_and((int)okF) != 0;
    int cls = okI ? 0 : (okF ? 1 : 2);

    for (int i = tid; i < BB * LL; i += 256) {
        unsigned int any = 0;
        #pragma unroll
        for (int h = 0; h < HISTN; h++) {
            int j = h * BB * LL + i;
            unsigned int v;
            if (cls == 0)      v = w[j];
            else if (cls == 1) v = (w[j] != 0u);
            else               v = m[j];
            any |= v;
        }
        g_mask[i] = any ? 1 : 0;
    }
}

// ---------------- tensor-core fused q+r GEMM ----------------
__global__ __launch_bounds__(256) void gemm_qr_tc(
    const float* __restrict__ A1, const float* __restrict__ A2,
    const float* __restrict__ Wq, const float* __restrict__ bq,
    const float* __restrict__ Wr, const float* __restrict__ br,
    float* __restrict__ Cq, float* __restrict__ Cr)
{
    __shared__ float Ash[64][36];
    __shared__ float Wqs[128][36];
    __shared__ float Wrs[128][36];

    int tid = threadIdx.x;
    int m0 = blockIdx.x * 64;
    int w = tid >> 5, lane = tid & 31;
    int qr = lane >> 2, qc = lane & 3;
    int wm = (w >> 2) * 32, wn = (w & 3) * 32;

    float accq[2][4][4], accr[2][4][4];
    #pragma unroll
    for (int mi = 0; mi < 2; mi++)
        #pragma unroll
        for (int ni = 0; ni < 4; ni++)
            #pragma unroll
            for (int j = 0; j < 4; j++) { accq[mi][ni][j] = 0.f; accr[mi][ni][j] = 0.f; }

    for (int k0 = 0; k0 < 128; k0 += 32) {
        #pragma unroll
        for (int i = 0; i < 2; i++) {
            int idx = tid + i * 256;
            int row = idx >> 3, c4 = (idx & 7) * 4;
            float4 a = *(const float4*)(A1 + (size_t)(m0 + row) * FF + k0 + c4);
            float4 b = *(const float4*)(A2 + (size_t)(m0 + row) * FF + k0 + c4);
            float4 o;
            o.x = __uint_as_float(tf32u(a.x + b.x));
            o.y = __uint_as_float(tf32u(a.y + b.y));
            o.z = __uint_as_float(tf32u(a.z + b.z));
            o.w = __uint_as_float(tf32u(a.w + b.w));
            *(float4*)&Ash[row][c4] = o;
        }
        #pragma unroll
        for (int i = 0; i < 4; i++) {
            int idx = tid + i * 256;
            int n = idx >> 3, c4 = (idx & 7) * 4;
            float4 a = *(const float4*)(Wq + (size_t)n * FF + k0 + c4);
            float4 o;
            o.x = __uint_as_float(tf32u(a.x)); o.y = __uint_as_float(tf32u(a.y));
            o.z = __uint_as_float(tf32u(a.z)); o.w = __uint_as_float(tf32u(a.w));
            *(float4*)&Wqs[n][c4] = o;
            float4 r = *(const float4*)(Wr + (size_t)n * FF + k0 + c4);
            float4 p;
            p.x = __uint_as_float(tf32u(r.x)); p.y = __uint_as_float(tf32u(r.y));
            p.z = __uint_as_float(tf32u(r.z)); p.w = __uint_as_float(tf32u(r.w));
            *(float4*)&Wrs[n][c4] = p;
        }
        __syncthreads();

        #pragma unroll
        for (int k8 = 0; k8 < 4; k8++) {
            int kk = k8 * 8;
            unsigned Af[2][4];
            #pragma unroll
            for (int mi = 0; mi < 2; mi++) {
                int r = wm + mi * 16 + qr;
                Af[mi][0] = __float_as_uint(Ash[r][kk + qc]);
                Af[mi][1] = __float_as_uint(Ash[r + 8][kk + qc]);
                Af[mi][2] = __float_as_uint(Ash[r][kk + qc + 4]);
                Af[mi][3] = __float_as_uint(Ash[r + 8][kk + qc + 4]);
            }
            #pragma unroll
            for (int ni = 0; ni < 4; ni++) {
                int n = wn + ni * 8 + qr;
                unsigned bq0 = __float_as_uint(Wqs[n][kk + qc]);
                unsigned bq1 = __float_as_uint(Wqs[n][kk + qc + 4]);
                unsigned br0 = __float_as_uint(Wrs[n][kk + qc]);
                unsigned br1 = __float_as_uint(Wrs[n][kk + qc + 4]);
                #pragma unroll
                for (int mi = 0; mi < 2; mi++) {
                    mma_tf32(accq[mi][ni], Af[mi], bq0, bq1);
                    mma_tf32(accr[mi][ni], Af[mi], br0, br1);
                }
            }
        }
        __syncthreads();
    }

    #pragma unroll
    for (int ni = 0; ni < 4; ni++) {
        int n = wn + ni * 8 + 2 * qc;
        float2 bq2 = *(const float2*)(bq + n);
        float2 br2 = *(const float2*)(br + n);
        #pragma unroll
        for (int mi = 0; mi < 2; mi++) {
            int r = m0 + wm + mi * 16 + qr;
            float2 o;
            o.x = accq[mi][ni][0] + bq2.x; o.y = accq[mi][ni][1] + bq2.y;
            *(float2*)(Cq + (size_t)r * FF + n) = o;
            o.x = accq[mi][ni][2] + bq2.x; o.y = accq[mi][ni][3] + bq2.y;
            *(float2*)(Cq + (size_t)(r + 8) * FF + n) = o;
            o.x = accr[mi][ni][0] + br2.x; o.y = accr[mi][ni][1] + br2.y;
            *(float2*)(Cr + (size_t)r * FF + n) = o;
            o.x = accr[mi][ni][2] + br2.x; o.y = accr[mi][ni][3] + br2.y;
            *(float2*)(Cr + (size_t)(r + 8) * FF + n) = o;
        }
    }
}

// ---------------- tensor-core combine GEMM ----------------
__global__ __launch_bounds__(256) void gemm_c_tc(
    const float* __restrict__ A, const float* __restrict__ W,
    const float* __restrict__ bias, float* __restrict__ C,
    const float* __restrict__ E1, const float* __restrict__ E2)
{
    __shared__ float Ash[64][36];
    __shared__ float Ws[128][36];

    int tid = threadIdx.x;
    int m0 = blockIdx.x * 64;
    int w = tid >> 5, lane = tid & 31;
    int qr = lane >> 2, qc = lane & 3;
    int wm = (w >> 2) * 32, wn = (w & 3) * 32;

    float acc[2][4][4];
    #pragma unroll
    for (int mi = 0; mi < 2; mi++)
        #pragma unroll
        for (int ni = 0; ni < 4; ni++)
            #pragma unroll
            for (int j = 0; j < 4; j++) acc[mi][ni][j] = 0.f;

    for (int k0 = 0; k0 < 128; k0 += 32) {
        #pragma unroll
        for (int i = 0; i < 2; i++) {
            int idx = tid + i * 256;
            int row = idx >> 3, c4 = (idx & 7) * 4;
            float4 a = *(const float4*)(A + (size_t)(m0 + row) * FF + k0 + c4);
            float4 o;
            o.x = __uint_as_float(tf32u(a.x)); o.y = __uint_as_float(tf32u(a.y));
            o.z = __uint_as_float(tf32u(a.z)); o.w = __uint_as_float(tf32u(a.w));
            *(float4*)&Ash[row][c4] = o;
        }
        #pragma unroll
        for (int i = 0; i < 4; i++) {
            int idx = tid + i * 256;
            int n = idx >> 3, c4 = (idx & 7) * 4;
            float4 a = *(const float4*)(W + (size_t)n * FF + k0 + c4);
            float4 o;
            o.x = __uint_as_float(tf32u(a.x)); o.y = __uint_as_float(tf32u(a.y));
            o.z = __uint_as_float(tf32u(a.z)); o.w = __uint_as_float(tf32u(a.w));
            *(float4*)&Ws[n][c4] = o;
        }
        __syncthreads();

        #pragma unroll
        for (int k8 = 0; k8 < 4; k8++) {
            int kk = k8 * 8;
            unsigned Af[2][4];
            #pragma unroll
            for (int mi = 0; mi < 2; mi++) {
                int r = wm + mi * 16 + qr;
                Af[mi][0] = __float_as_uint(Ash[r][kk + qc]);
                Af[mi][1] = __float_as_uint(Ash[r + 8][kk + qc]);
                Af[mi][2] = __float_as_uint(Ash[r][kk + qc + 4]);
                Af[mi][3] = __float_as_uint(Ash[r + 8][kk + qc + 4]);
            }
            #pragma unroll
            for (int ni = 0; ni < 4; ni++) {
                int n = wn + ni * 8 + qr;
                unsigned b0 = __float_as_uint(Ws[n][kk + qc]);
                unsigned b1 = __float_as_uint(Ws[n][kk + qc + 4]);
                #pragma unroll
                for (int mi = 0; mi < 2; mi++)
                    mma_tf32(acc[mi][ni], Af[mi], b0, b1);
            }
        }
        __syncthreads();
    }

    #pragma unroll
    for (int ni = 0; ni < 4; ni++) {
        int n = wn + ni * 8 + 2 * qc;
        float2 b2 = *(const float2*)(bias + n);
        #pragma unroll
        for (int mi = 0; mi < 2; mi++) {
            int r = m0 + wm + mi * 16 + qr;
            float2 e1 = *(const float2*)(E1 + (size_t)r * FF + n);
            float2 e2 = *(const float2*)(E2 + (size_t)r * FF + n);
            float2 o;
            o.x = acc[mi][ni][0] + b2.x + e1.x - e2.x;
            o.y = acc[mi][ni][1] + b2.y + e1.y - e2.y;
            *(float2*)(C + (size_t)r * FF + n) = o;
            e1 = *(const float2*)(E1 + (size_t)(r + 8) * FF + n);
            e2 = *(const float2*)(E2 + (size_t)(r + 8) * FF + n);
            o.x = acc[mi][ni][2] + b2.x + e1.x - e2.x;
            o.y = acc[mi][ni][3] + b2.y + e1.y - e2.y;
            *(float2*)(C + (size_t)(r + 8) * FF + n) = o;
        }
    }
}

// ---------------- attention v10: register-resident p, quad softmax ----------------
// Stage-A C-fragment ownership == Stage-B A-fragment ownership, so p never
// touches smem. Softmax: quad shfl (2 lvl) + cross-warp via wmax/wsum [8][32].
// smem: qsh 640 + wmax 256 + wsum 256 + pb 4160 + sinv 32 = 5344 floats (21.4KB)
#define ATB 6
#define CSM_Q    0
#define CSM_WMAX 640
#define CSM_WSUM 896
#define CSM_PB   1152
#define CSM_SI   5312
#define CSMEM_BYTES (5344 * 4)
#define SCALE_LOG2E 0.3606737602222409f

__global__ __launch_bounds__(256) void attn10_kernel()
{
    extern __shared__ float smp[];
    float* qsh  = smp + CSM_Q;     // [32][20] tf32
    float* wmax = smp + CSM_WMAX;  // [8][32]
    float* wsum = smp + CSM_WSUM;  // [8][32]
    float* pb   = smp + CSM_PB;    // [8][520]
    float* sinv = smp + CSM_SI;    // [32]

    int tid = threadIdx.x;
    int b = blockIdx.x >> 3, h = blockIdx.x & 7;
    int t0 = blockIdx.y * ATB;
    int w = tid >> 5, lane = tid & 31;
    int qr = lane >> 2, qc = lane & 3;

    // ---- hoisted t-invariant fragments ----
    unsigned Kb[4][4];
    #pragma unroll
    for (int ni = 0; ni < 4; ni++) {
        int n = w * 32 + ni * 8 + qr;
        const float* kp = g_Kproj + ((size_t)(b * LL + n)) * FF + h * DHH;
        Kb[ni][0] = tf32u(kp[qc]);
        Kb[ni][1] = tf32u(kp[qc + 4]);
        Kb[ni][2] = tf32u(kp[qc + 8]);
        Kb[ni][3] = tf32u(kp[qc + 12]);
    }
    unsigned LVh[2][2][2];
    #pragma unroll
    for (int ki = 0; ki < 2; ki++) {
        int kk = w * 32 + ki * 16;
        #pragma unroll
        for (int ni = 0; ni < 2; ni++) {
            int d = ni * 8 + qr;
            const float* base = g_LV + ((size_t)(b * LL)) * FF + h * DHH + d;
            float x0 = base[(size_t)(kk + 2 * qc) * FF];
            float x1 = base[(size_t)(kk + 2 * qc + 1) * FF];
            float x2 = base[(size_t)(kk + 2 * qc + 8) * FF];
            float x3 = base[(size_t)(kk + 2 * qc + 9) * FF];
            LVh[ki][ni][0] = packh2(x0, x1);
            LVh[ki][ni][1] = packh2(x2, x3);
        }
    }
    unsigned mbits = 0;
    #pragma unroll
    for (int ni = 0; ni < 4; ni++) {
        int n = w * 32 + ni * 8 + 2 * qc;
        if (g_mask[b * LL + n])     mbits |= 1u << (ni * 2);
        if (g_mask[b * LL + n + 1]) mbits |= 1u << (ni * 2 + 1);
    }

    for (int t = t0; t < t0 + ATB; t++) {
        __syncthreads();                        // qsh/pb/wmax WAR
        if (tid < 128) {
            int v = tid >> 2, c4 = (tid & 3) * 4;
            float4 qv = *(const float4*)(g_q + ((size_t)((t * BB + b) * VV + v)) * FF + h * DHH + c4);
            qsh[v * 20 + c4 + 0] = __uint_as_float(tf32u(qv.x));
            qsh[v * 20 + c4 + 1] = __uint_as_float(tf32u(qv.y));
            qsh[v * 20 + c4 + 2] = __uint_as_float(tf32u(qv.z));
            qsh[v * 20 + c4 + 3] = __uint_as_float(tf32u(qv.w));
        }
        __syncthreads();

        // ---- Stage A: scores in regs ----
        float Cs[2][4][4];
        {
            unsigned Aq[2][2][4];
            #pragma unroll
            for (int mi = 0; mi < 2; mi++)
                #pragma unroll
                for (int ki = 0; ki < 2; ki++) {
                    int r = mi * 16 + qr;
                    Aq[mi][ki][0] = __float_as_uint(qsh[r * 20 + ki * 8 + qc]);
                    Aq[mi][ki][1] = __float_as_uint(qsh[(r + 8) * 20 + ki * 8 + qc]);
                    Aq[mi][ki][2] = __float_as_uint(qsh[r * 20 + ki * 8 + qc + 4]);
                    Aq[mi][ki][3] = __float_as_uint(qsh[(r + 8) * 20 + ki * 8 + qc + 4]);
                }
            #pragma unroll
            for (int mi = 0; mi < 2; mi++)
                #pragma unroll
                for (int ni = 0; ni < 4; ni++)
                    #pragma unroll
                    for (int j = 0; j < 4; j++) Cs[mi][ni][j] = 0.f;
            #pragma unroll
            for (int ni = 0; ni < 4; ni++)
                #pragma unroll
                for (int mi = 0; mi < 2; mi++) {
                    mma_tf32(Cs[mi][ni], Aq[mi][0], Kb[ni][0], Kb[ni][1]);
                    mma_tf32(Cs[mi][ni], Aq[mi][1], Kb[ni][2], Kb[ni][3]);
                }
        }
        // mask + scale (log2 domain) in regs
        #pragma unroll
        for (int mi = 0; mi < 2; mi++)
            #pragma unroll
            for (int ni = 0; ni < 4; ni++) {
                bool m0 = (mbits >> (ni * 2)) & 1;
                bool m1 = (mbits >> (ni * 2 + 1)) & 1;
                Cs[mi][ni][0] = m0 ? Cs[mi][ni][0] * SCALE_LOG2E : -1e9f;
                Cs[mi][ni][1] = m1 ? Cs[mi][ni][1] * SCALE_LOG2E : -1e9f;
                Cs[mi][ni][2] = m0 ? Cs[mi][ni][2] * SCALE_LOG2E : -1e9f;
                Cs[mi][ni][3] = m1 ? Cs[mi][ni][3] * SCALE_LOG2E : -1e9f;
            }

        // ---- row max: quad reduce + cross-warp partials ----
        #pragma unroll
        for (int mi = 0; mi < 2; mi++) {
            float a0 = -1e30f, a1 = -1e30f;
            #pragma unroll
            for (int ni = 0; ni < 4; ni++) {
                a0 = fmaxf(a0, fmaxf(Cs[mi][ni][0], Cs[mi][ni][1]));
                a1 = fmaxf(a1, fmaxf(Cs[mi][ni][2], Cs[mi][ni][3]));
            }
            a0 = fmaxf(a0, __shfl_xor_sync(0xffffffffu, a0, 1));
            a0 = fmaxf(a0, __shfl_xor_sync(0xffffffffu, a0, 2));
            a1 = fmaxf(a1, __shfl_xor_sync(0xffffffffu, a1, 1));
            a1 = fmaxf(a1, __shfl_xor_sync(0xffffffffu, a1, 2));
            if (qc == 0) {
                wmax[w * 32 + mi * 16 + qr] = a0;
                wmax[w * 32 + mi * 16 + qr + 8] = a1;
            }
        }
        __syncthreads();

        // ---- exp into stage-B A-fragments (regs) + row sums ----
        unsigned Ap[2][2][4];
        #pragma unroll
        for (int mi = 0; mi < 2; mi++) {
            int r0 = mi * 16 + qr, r1 = r0 + 8;
            float m0 = wmax[r0], m1 = wmax[r1];
            #pragma unroll
            for (int ww = 1; ww < 8; ww++) {
                m0 = fmaxf(m0, wmax[ww * 32 + r0]);
                m1 = fmaxf(m1, wmax[ww * 32 + r1]);
            }
            __half2 hs0 = __floats2half2_rn(0.f, 0.f);
            __half2 hs1 = hs0;
            #pragma unroll
            for (int ki = 0; ki < 2; ki++)
                #pragma unroll
                for (int c = 0; c < 2; c++) {
                    int ni = 2 * ki + c;
                    unsigned wlo = h2ex2(packh2(Cs[mi][ni][0] - m0, Cs[mi][ni][1] - m0));
                    unsigned whi = h2ex2(packh2(Cs[mi][ni][2] - m1, Cs[mi][ni][3] - m1));
                    Ap[mi][ki][2 * c]     = wlo;
                    Ap[mi][ki][2 * c + 1] = whi;
                    hs0 = __hadd2(hs0, *(__half2*)&wlo);
                    hs1 = __hadd2(hs1, *(__half2*)&whi);
                }
            float s0 = __low2float(hs0) + __high2float(hs0);
            float s1 = __low2float(hs1) + __high2float(hs1);
            s0 += __shfl_xor_sync(0xffffffffu, s0, 1);
            s0 += __shfl_xor_sync(0xffffffffu, s0, 2);
            s1 += __shfl_xor_sync(0xffffffffu, s1, 1);
            s1 += __shfl_xor_sync(0xffffffffu, s1, 2);
            if (qc == 0) {
                wsum[w * 32 + r0] = s0;
                wsum[w * 32 + r1] = s1;
            }
        }
        __syncthreads();

        // warp 0 finalizes 1/sum
        if (w == 0 && qc == 0) {
            #pragma unroll
            for (int g = 0; g < 4; g++) {
                int row = qr + g * 8;
                float s = wsum[row];
                #pragma unroll
                for (int ww = 1; ww < 8; ww++) s += wsum[ww * 32 + row];
                sinv[row] = __fdividef(1.f, s);
            }
        }

        // ---- Stage B: p @ LV from regs (k-split across warps) ----
        float Co[2][2][4];
        #pragma unroll
        for (int mi = 0; mi < 2; mi++)
            #pragma unroll
            for (int ni = 0; ni < 2; ni++)
                #pragma unroll
                for (int j = 0; j < 4; j++) Co[mi][ni][j] = 0.f;
        #pragma unroll
        for (int ki = 0; ki < 2; ki++)
            #pragma unroll
            for (int ni = 0; ni < 2; ni++)
                #pragma unroll
                for (int mi = 0; mi < 2; mi++)
                    mma_f16(Co[mi][ni], Ap[mi][ki], LVh[ki][ni][0], LVh[ki][ni][1]);

        #pragma unroll
        for (int mi = 0; mi < 2; mi++)
            #pragma unroll
            for (int ni = 0; ni < 2; ni++) {
                int v = mi * 16 + qr;
                int d = ni * 8 + 2 * qc;
                float2 p01, p23;
                p01.x = Co[mi][ni][0]; p01.y = Co[mi][ni][1];
                p23.x = Co[mi][ni][2]; p23.y = Co[mi][ni][3];
                *(float2*)&pb[w * 520 + v * 16 + d] = p01;
                *(float2*)&pb[w * 520 + (v + 8) * 16 + d] = p23;
            }
        __syncthreads();

        // ---- cross-warp reduce + exp epilogue ----
        {
            int v = tid >> 3;
            int d = (tid & 7) * 2;
            float2 s = make_float2(0.f, 0.f);
            #pragma unroll
            for (int ww = 0; ww < 8; ww++) {
                float2 p = *(float2*)&pb[ww * 520 + tid * 2];
                s.x += p.x; s.y += p.y;
            }
            float si = sinv[v];
            float2 r2 = *(const float2*)(g_r + ((size_t)((t * BB + b) * VV + v)) * FF + h * DHH + d);
            float2 res;
            res.x = r2.x * __expf(s.x * si);
            res.y = r2.y * __expf(s.y * si);
            *(float2*)(g_pre + ((size_t)(t * BB + b)) * (VV * FF)
                       + h * (VV * DHH) + v * DHH + d) = res;
        }
    }
}

// ---------------- launch ----------------
extern "C" void kernel_launch(void* const* d_in, const int* in_sizes, int n_in,
                              void* d_out, int out_size)
{
    const float* vehicles    = (const float*)d_in[0];
    const float* initial_pos = (const float*)d_in[1];
    const float* lanes       = (const float*)d_in[2];
    const unsigned char* mask_lanes = (const unsigned char*)d_in[3];
    const float* Wk = (const float*)d_in[4];
    const float* bk = (const float*)d_in[5];
    const float* Wv = (const float*)d_in[6];
    const float* bv = (const float*)d_in[7];
    const float* Wq = (const float*)d_in[8];
    const float* bq = (const float*)d_in[9];
    const float* Wr = (const float*)d_in[10];
    const float* br = (const float*)d_in[11];
    const float* Wc = (const float*)d_in[12];
    const float* bc = (const float*)d_in[13];
    float* out = (float*)d_out;

    cudaFuncSetAttribute(attn10_kernel,
                         cudaFuncAttributeMaxDynamicSharedMemorySize, CSMEM_BYTES);

    float *gK, *gLV, *gq, *gr, *gpre;
    cudaGetSymbolAddress((void**)&gK,   g_Kproj);
    cudaGetSymbolAddress((void**)&gLV,  g_LV);
    cudaGetSymbolAddress((void**)&gq,   g_q);
    cudaGetSymbolAddress((void**)&gr,   g_r);
    cudaGetSymbolAddress((void**)&gpre, g_pre);

    // 1) lane projections + mask
    lane_proj_kernel<false><<<BB * LL / 32, 256>>>(lanes, Wk, bk, gK);
    lane_proj_kernel<true ><<<BB * LL / 32, 256>>>(lanes, Wv, bv, gLV);
    mask_kernel<<<1, 256>>>(mask_lanes);

    // 2) fused q, r projections (tensor cores)
    gemm_qr_tc<<<MROWS / 64, 256>>>(vehicles, initial_pos, Wq, bq, Wr, br, gq, gr);

    // 3) attention (register-resident p)
    attn10_kernel<<<dim3(BB * HH, TT / ATB), 256, CSMEM_BYTES>>>();

    // 4) combine + residual (tensor cores)
    gemm_c_tc<<<MROWS / 64, 256>>>(gpre, Wc, bc, out, vehicles, initial_pos);
}

// round 17
// speedup vs baseline: 1.3515x; 1.3515x over previous
#include <cuda_runtime.h>
#include <cuda_fp16.h>
#include <math.h>

#define TT   30
#define BB   32
#define VV   32
#define FF   128
#define LL   256
#define LFF  64
#define HH   8
#define DHH  16
#define HISTN 10
#define MROWS (TT*BB*VV)   // 30720

// ---- mma helpers ----
__device__ __forceinline__ unsigned tf32u(float x) {
    unsigned u; asm("cvt.rna.tf32.f32 %0,%1;" : "=r"(u) : "f"(x)); return u;
}
__device__ __forceinline__ void mma_tf32(float* c, const unsigned* a, unsigned b0, unsigned b1) {
    asm volatile("mma.sync.aligned.m16n8k8.row.col.f32.tf32.tf32.f32 "
        "{%0,%1,%2,%3},{%4,%5,%6,%7},{%8,%9},{%0,%1,%2,%3};"
        : "+f"(c[0]), "+f"(c[1]), "+f"(c[2]), "+f"(c[3])
        : "r"(a[0]), "r"(a[1]), "r"(a[2]), "r"(a[3]), "r"(b0), "r"(b1));
}
__device__ __forceinline__ void mma_f16(float* c, const unsigned* a, unsigned b0, unsigned b1) {
    asm volatile("mma.sync.aligned.m16n8k16.row.col.f32.f16.f16.f32 "
        "{%0,%1,%2,%3},{%4,%5,%6,%7},{%8,%9},{%0,%1,%2,%3};"
        : "+f"(c[0]), "+f"(c[1]), "+f"(c[2]), "+f"(c[3])
        : "r"(a[0]), "r"(a[1]), "r"(a[2]), "r"(a[3]), "r"(b0), "r"(b1));
}
__device__ __forceinline__ unsigned h2ex2(unsigned h) {
    unsigned r; asm("ex2.approx.f16x2 %0,%1;" : "=r"(r) : "r"(h)); return r;
}
__device__ __forceinline__ unsigned packh2(float a, float b) {
    __half2 h = __floats2half2_rn(a, b); return *(unsigned*)&h;
}

// ---------------- scratch ----------------
__device__ float g_Kproj[BB*LL*FF];
__device__ float g_LV[BB*LL*FF];
__device__ unsigned char g_mask[BB*LL];
__device__ float g_q[MROWS*FF];
__device__ float g_r[MROWS*FF];
__device__ float g_pre[MROWS*FF];

// ---------------- fused lane projection: K and logsig(V) in one pass ----------------
// dynamic smem: WkS [64][129] + WvS [64][129] + lsh [32][64] + bkS[128] + bvS[128]
#define LP_WK   0
#define LP_WV   8256
#define LP_LSH  16512
#define LP_BK   18560
#define LP_BV   18688
#define LP_FLOATS 18816
#define LP_BYTES (LP_FLOATS * 4)

__global__ __launch_bounds__(256) void lane_proj2_kernel(
    const float* __restrict__ lanes,
    const float* __restrict__ Wk, const float* __restrict__ bk,
    const float* __restrict__ Wv, const float* __restrict__ bv,
    float* __restrict__ outK, float* __restrict__ outLV)
{
    extern __shared__ float s[];
    float* WkS = s + LP_WK;
    float* WvS = s + LP_WV;
    float* lsh = s + LP_LSH;
    float* bkS = s + LP_BK;
    float* bvS = s + LP_BV;

    int tid = threadIdx.x;
    int row0 = blockIdx.x * 32;

    #pragma unroll
    for (int i = 0; i < 32; i++) {       // 8192 weights each
        int idx = tid + i * 256;
        int f = idx >> 6, j = idx & 63;
        WkS[j * 129 + f] = Wk[idx];
        WvS[j * 129 + f] = Wv[idx];
    }
    if (tid < FF) { bkS[tid] = bk[tid]; bvS[tid] = bv[tid]; }
    #pragma unroll
    for (int i = 0; i < 2; i++) {        // 32 rows x 64 floats of lanes
        int idx = tid + i * 256;
        int r = idx >> 4;
        int c = (idx & 15) * 4;
        *(float4*)&lsh[r * 64 + c] = *(const float4*)(lanes + (size_t)(row0 + r) * LFF + c);
    }
    __syncthreads();

    int f = tid & 127;
    for (int r = tid >> 7; r < 32; r += 2) {
        float accK = bkS[f], accV = bvS[f];
        #pragma unroll
        for (int j = 0; j < LFF; j++) {
            float l = lsh[r * 64 + j];
            accK += l * WkS[j * 129 + f];
            accV += l * WvS[j * 129 + f];
        }
        size_t o = (size_t)(row0 + r) * FF + f;
        outK[o] = accK;
        outLV[o] = (accV >= 0.f) ? -__logf(1.f + __expf(-accV))
                                 : accV - __logf(1.f + __expf(accV));
    }
}

// ---------------- mask ----------------
__global__ void mask_kernel(const unsigned char* __restrict__ m)
{
    int tid = threadIdx.x;
    const unsigned int* w = (const unsigned int*)m;
    bool okI = true, okF = true;
    for (int j = tid; j < (HISTN * BB * LL) / 4; j += 256) {
        unsigned int x = w[j];
        if (x > 1u) okI = false;
        if (x != 0u && x != 0x3F800000u) okF = false;
    }
    okI = __syncthreads_and((int)okI) != 0;
    okF = __syncthreads_and((int)okF) != 0;
    int cls = okI ? 0 : (okF ? 1 : 2);

    for (int i = tid; i < BB * LL; i += 256) {
        unsigned int any = 0;
        #pragma unroll
        for (int h = 0; h < HISTN; h++) {
            int j = h * BB * LL + i;
            unsigned int v;
            if (cls == 0)      v = w[j];
            else if (cls == 1) v = (w[j] != 0u);
            else               v = m[j];
            any |= v;
        }
        g_mask[i] = any ? 1 : 0;
    }
}

// ---------------- tensor-core fused q+r GEMM ----------------
__global__ __launch_bounds__(256) void gemm_qr_tc(
    const float* __restrict__ A1, const float* __restrict__ A2,
    const float* __restrict__ Wq, const float* __restrict__ bq,
    const float* __restrict__ Wr, const float* __restrict__ br,
    float* __restrict__ Cq, float* __restrict__ Cr)
{
    __shared__ float Ash[64][36];
    __shared__ float Wqs[128][36];
    __shared__ float Wrs[128][36];

    int tid = threadIdx.x;
    int m0 = blockIdx.x * 64;
    int w = tid >> 5, lane = tid & 31;
    int qr = lane >> 2, qc = lane & 3;
    int wm = (w >> 2) * 32, wn = (w & 3) * 32;

    float accq[2][4][4], accr[2][4][4];
    #pragma unroll
    for (int mi = 0; mi < 2; mi++)
        #pragma unroll
        for (int ni = 0; ni < 4; ni++)
            #pragma unroll
            for (int j = 0; j < 4; j++) { accq[mi][ni][j] = 0.f; accr[mi][ni][j] = 0.f; }

    for (int k0 = 0; k0 < 128; k0 += 32) {
        #pragma unroll
        for (int i = 0; i < 2; i++) {
            int idx = tid + i * 256;
            int row = idx >> 3, c4 = (idx & 7) * 4;
            float4 a = *(const float4*)(A1 + (size_t)(m0 + row) * FF + k0 + c4);
            float4 b = *(const float4*)(A2 + (size_t)(m0 + row) * FF + k0 + c4);
            float4 o;
            o.x = __uint_as_float(tf32u(a.x + b.x));
            o.y = __uint_as_float(tf32u(a.y + b.y));
            o.z = __uint_as_float(tf32u(a.z + b.z));
            o.w = __uint_as_float(tf32u(a.w + b.w));
            *(float4*)&Ash[row][c4] = o;
        }
        #pragma unroll
        for (int i = 0; i < 4; i++) {
            int idx = tid + i * 256;
            int n = idx >> 3, c4 = (idx & 7) * 4;
            float4 a = *(const float4*)(Wq + (size_t)n * FF + k0 + c4);
            float4 o;
            o.x = __uint_as_float(tf32u(a.x)); o.y = __uint_as_float(tf32u(a.y));
            o.z = __uint_as_float(tf32u(a.z)); o.w = __uint_as_float(tf32u(a.w));
            *(float4*)&Wqs[n][c4] = o;
            float4 r = *(const float4*)(Wr + (size_t)n * FF + k0 + c4);
            float4 p;
            p.x = __uint_as_float(tf32u(r.x)); p.y = __uint_as_float(tf32u(r.y));
            p.z = __uint_as_float(tf32u(r.z)); p.w = __uint_as_float(tf32u(r.w));
            *(float4*)&Wrs[n][c4] = p;
        }
        __syncthreads();

        #pragma unroll
        for (int k8 = 0; k8 < 4; k8++) {
            int kk = k8 * 8;
            unsigned Af[2][4];
            #pragma unroll
            for (int mi = 0; mi < 2; mi++) {
                int r = wm + mi * 16 + qr;
                Af[mi][0] = __float_as_uint(Ash[r][kk + qc]);
                Af[mi][1] = __float_as_uint(Ash[r + 8][kk + qc]);
                Af[mi][2] = __float_as_uint(Ash[r][kk + qc + 4]);
                Af[mi][3] = __float_as_uint(Ash[r + 8][kk + qc + 4]);
            }
            #pragma unroll
            for (int ni = 0; ni < 4; ni++) {
                int n = wn + ni * 8 + qr;
                unsigned bq0 = __float_as_uint(Wqs[n][kk + qc]);
                unsigned bq1 = __float_as_uint(Wqs[n][kk + qc + 4]);
                unsigned br0 = __float_as_uint(Wrs[n][kk + qc]);
                unsigned br1 = __float_as_uint(Wrs[n][kk + qc + 4]);
                #pragma unroll
                for (int mi = 0; mi < 2; mi++) {
                    mma_tf32(accq[mi][ni], Af[mi], bq0, bq1);
                    mma_tf32(accr[mi][ni], Af[mi], br0, br1);
                }
            }
        }
        __syncthreads();
    }

    #pragma unroll
    for (int ni = 0; ni < 4; ni++) {
        int n = wn + ni * 8 + 2 * qc;
        float2 bq2 = *(const float2*)(bq + n);
        float2 br2 = *(const float2*)(br + n);
        #pragma unroll
        for (int mi = 0; mi < 2; mi++) {
            int r = m0 + wm + mi * 16 + qr;
            float2 o;
            o.x = accq[mi][ni][0] + bq2.x; o.y = accq[mi][ni][1] + bq2.y;
            *(float2*)(Cq + (size_t)r * FF + n) = o;
            o.x = accq[mi][ni][2] + bq2.x; o.y = accq[mi][ni][3] + bq2.y;
            *(float2*)(Cq + (size_t)(r + 8) * FF + n) = o;
            o.x = accr[mi][ni][0] + br2.x; o.y = accr[mi][ni][1] + br2.y;
            *(float2*)(Cr + (size_t)r * FF + n) = o;
            o.x = accr[mi][ni][2] + br2.x; o.y = accr[mi][ni][3] + br2.y;
            *(float2*)(Cr + (size_t)(r + 8) * FF + n) = o;
        }
    }
}

// ---------------- tensor-core combine GEMM ----------------
__global__ __launch_bounds__(256) void gemm_c_tc(
    const float* __restrict__ A, const float* __restrict__ W,
    const float* __restrict__ bias, float* __restrict__ C,
    const float* __restrict__ E1, const float* __restrict__ E2)
{
    __shared__ float Ash[64][36];
    __shared__ float Ws[128][36];

    int tid = threadIdx.x;
    int m0 = blockIdx.x * 64;
    int w = tid >> 5, lane = tid & 31;
    int qr = lane >> 2, qc = lane & 3;
    int wm = (w >> 2) * 32, wn = (w & 3) * 32;

    float acc[2][4][4];
    #pragma unroll
    for (int mi = 0; mi < 2; mi++)
        #pragma unroll
        for (int ni = 0; ni < 4; ni++)
            #pragma unroll
            for (int j = 0; j < 4; j++) acc[mi][ni][j] = 0.f;

    for (int k0 = 0; k0 < 128; k0 += 32) {
        #pragma unroll
        for (int i = 0; i < 2; i++) {
            int idx = tid + i * 256;
            int row = idx >> 3, c4 = (idx & 7) * 4;
            float4 a = *(const float4*)(A + (size_t)(m0 + row) * FF + k0 + c4);
            float4 o;
            o.x = __uint_as_float(tf32u(a.x)); o.y = __uint_as_float(tf32u(a.y));
            o.z = __uint_as_float(tf32u(a.z)); o.w = __uint_as_float(tf32u(a.w));
            *(float4*)&Ash[row][c4] = o;
        }
        #pragma unroll
        for (int i = 0; i < 4; i++) {
            int idx = tid + i * 256;
            int n = idx >> 3, c4 = (idx & 7) * 4;
            float4 a = *(const float4*)(W + (size_t)n * FF + k0 + c4);
            float4 o;
            o.x = __uint_as_float(tf32u(a.x)); o.y = __uint_as_float(tf32u(a.y));
            o.z = __uint_as_float(tf32u(a.z)); o.w = __uint_as_float(tf32u(a.w));
            *(float4*)&Ws[n][c4] = o;
        }
        __syncthreads();

        #pragma unroll
        for (int k8 = 0; k8 < 4; k8++) {
            int kk = k8 * 8;
            unsigned Af[2][4];
            #pragma unroll
            for (int mi = 0; mi < 2; mi++) {
                int r = wm + mi * 16 + qr;
                Af[mi][0] = __float_as_uint(Ash[r][kk + qc]);
                Af[mi][1] = __float_as_uint(Ash[r + 8][kk + qc]);
                Af[mi][2] = __float_as_uint(Ash[r][kk + qc + 4]);
                Af[mi][3] = __float_as_uint(Ash[r + 8][kk + qc + 4]);
            }
            #pragma unroll
            for (int ni = 0; ni < 4; ni++) {
                int n = wn + ni * 8 + qr;
                unsigned b0 = __float_as_uint(Ws[n][kk + qc]);
                unsigned b1 = __float_as_uint(Ws[n][kk + qc + 4]);
                #pragma unroll
                for (int mi = 0; mi < 2; mi++)
                    mma_tf32(acc[mi][ni], Af[mi], b0, b1);
            }
        }
        __syncthreads();
    }

    #pragma unroll
    for (int ni = 0; ni < 4; ni++) {
        int n = wn + ni * 8 + 2 * qc;
        float2 b2 = *(const float2*)(bias + n);
        #pragma unroll
        for (int mi = 0; mi < 2; mi++) {
            int r = m0 + wm + mi * 16 + qr;
            float2 e1 = *(const float2*)(E1 + (size_t)r * FF + n);
            float2 e2 = *(const float2*)(E2 + (size_t)r * FF + n);
            float2 o;
            o.x = acc[mi][ni][0] + b2.x + e1.x - e2.x;
            o.y = acc[mi][ni][1] + b2.y + e1.y - e2.y;
            *(float2*)(C + (size_t)r * FF + n) = o;
            e1 = *(const float2*)(E1 + (size_t)(r + 8) * FF + n);
            e2 = *(const float2*)(E2 + (size_t)(r + 8) * FF + n);
            o.x = acc[mi][ni][2] + b2.x + e1.x - e2.x;
            o.y = acc[mi][ni][3] + b2.y + e1.y - e2.y;
            *(float2*)(C + (size_t)(r + 8) * FF + n) = o;
        }
    }
}

// ---------------- attention v10: register-resident p, quad softmax (retest) ----------------
#define ATB 6
#define CSM_Q    0
#define CSM_WMAX 640
#define CSM_WSUM 896
#define CSM_PB   1152
#define CSM_SI   5312
#define CSMEM_BYTES (5344 * 4)
#define SCALE_LOG2E 0.3606737602222409f

__global__ __launch_bounds__(256) void attn10_kernel()
{
    extern __shared__ float smp[];
    float* qsh  = smp + CSM_Q;
    float* wmax = smp + CSM_WMAX;
    float* wsum = smp + CSM_WSUM;
    float* pb   = smp + CSM_PB;
    float* sinv = smp + CSM_SI;

    int tid = threadIdx.x;
    int b = blockIdx.x >> 3, h = blockIdx.x & 7;
    int t0 = blockIdx.y * ATB;
    int w = tid >> 5, lane = tid & 31;
    int qr = lane >> 2, qc = lane & 3;

    unsigned Kb[4][4];
    #pragma unroll
    for (int ni = 0; ni < 4; ni++) {
        int n = w * 32 + ni * 8 + qr;
        const float* kp = g_Kproj + ((size_t)(b * LL + n)) * FF + h * DHH;
        Kb[ni][0] = tf32u(kp[qc]);
        Kb[ni][1] = tf32u(kp[qc + 4]);
        Kb[ni][2] = tf32u(kp[qc + 8]);
        Kb[ni][3] = tf32u(kp[qc + 12]);
    }
    unsigned LVh[2][2][2];
    #pragma unroll
    for (int ki = 0; ki < 2; ki++) {
        int kk = w * 32 + ki * 16;
        #pragma unroll
        for (int ni = 0; ni < 2; ni++) {
            int d = ni * 8 + qr;
            const float* base = g_LV + ((size_t)(b * LL)) * FF + h * DHH + d;
            float x0 = base[(size_t)(kk + 2 * qc) * FF];
            float x1 = base[(size_t)(kk + 2 * qc + 1) * FF];
            float x2 = base[(size_t)(kk + 2 * qc + 8) * FF];
            float x3 = base[(size_t)(kk + 2 * qc + 9) * FF];
            LVh[ki][ni][0] = packh2(x0, x1);
            LVh[ki][ni][1] = packh2(x2, x3);
        }
    }
    unsigned mbits = 0;
    #pragma unroll
    for (int ni = 0; ni < 4; ni++) {
        int n = w * 32 + ni * 8 + 2 * qc;
        if (g_mask[b * LL + n])     mbits |= 1u << (ni * 2);
        if (g_mask[b * LL + n + 1]) mbits |= 1u << (ni * 2 + 1);
    }

    for (int t = t0; t < t0 + ATB; t++) {
        __syncthreads();
        if (tid < 128) {
            int v = tid >> 2, c4 = (tid & 3) * 4;
            float4 qv = *(const float4*)(g_q + ((size_t)((t * BB + b) * VV + v)) * FF + h * DHH + c4);
            qsh[v * 20 + c4 + 0] = __uint_as_float(tf32u(qv.x));
            qsh[v * 20 + c4 + 1] = __uint_as_float(tf32u(qv.y));
            qsh[v * 20 + c4 + 2] = __uint_as_float(tf32u(qv.z));
            qsh[v * 20 + c4 + 3] = __uint_as_float(tf32u(qv.w));
        }
        __syncthreads();

        float Cs[2][4][4];
        {
            unsigned Aq[2][2][4];
            #pragma unroll
            for (int mi = 0; mi < 2; mi++)
                #pragma unroll
                for (int ki = 0; ki < 2; ki++) {
                    int r = mi * 16 + qr;
                    Aq[mi][ki][0] = __float_as_uint(qsh[r * 20 + ki * 8 + qc]);
                    Aq[mi][ki][1] = __float_as_uint(qsh[(r + 8) * 20 + ki * 8 + qc]);
                    Aq[mi][ki][2] = __float_as_uint(qsh[r * 20 + ki * 8 + qc + 4]);
                    Aq[mi][ki][3] = __float_as_uint(qsh[(r + 8) * 20 + ki * 8 + qc + 4]);
                }
            #pragma unroll
            for (int mi = 0; mi < 2; mi++)
                #pragma unroll
                for (int ni = 0; ni < 4; ni++)
                    #pragma unroll
                    for (int j = 0; j < 4; j++) Cs[mi][ni][j] = 0.f;
            #pragma unroll
            for (int ni = 0; ni < 4; ni++)
                #pragma unroll
                for (int mi = 0; mi < 2; mi++) {
                    mma_tf32(Cs[mi][ni], Aq[mi][0], Kb[ni][0], Kb[ni][1]);
                    mma_tf32(Cs[mi][ni], Aq[mi][1], Kb[ni][2], Kb[ni][3]);
                }
        }
        #pragma unroll
        for (int mi = 0; mi < 2; mi++)
            #pragma unroll
            for (int ni = 0; ni < 4; ni++) {
                bool m0 = (mbits >> (ni * 2)) & 1;
                bool m1 = (mbits >> (ni * 2 + 1)) & 1;
                Cs[mi][ni][0] = m0 ? Cs[mi][ni][0] * SCALE_LOG2E : -1e9f;
                Cs[mi][ni][1] = m1 ? Cs[mi][ni][1] * SCALE_LOG2E : -1e9f;
                Cs[mi][ni][2] = m0 ? Cs[mi][ni][2] * SCALE_LOG2E : -1e9f;
                Cs[mi][ni][3] = m1 ? Cs[mi][ni][3] * SCALE_LOG2E : -1e9f;
            }

        #pragma unroll
        for (int mi = 0; mi < 2; mi++) {
            float a0 = -1e30f, a1 = -1e30f;
            #pragma unroll
            for (int ni = 0; ni < 4; ni++) {
                a0 = fmaxf(a0, fmaxf(Cs[mi][ni][0], Cs[mi][ni][1]));
                a1 = fmaxf(a1, fmaxf(Cs[mi][ni][2], Cs[mi][ni][3]));
            }
            a0 = fmaxf(a0, __shfl_xor_sync(0xffffffffu, a0, 1));
            a0 = fmaxf(a0, __shfl_xor_sync(0xffffffffu, a0, 2));
            a1 = fmaxf(a1, __shfl_xor_sync(0xffffffffu, a1, 1));
            a1 = fmaxf(a1, __shfl_xor_sync(0xffffffffu, a1, 2));
            if (qc == 0) {
                wmax[w * 32 + mi * 16 + qr] = a0;
                wmax[w * 32 + mi * 16 + qr + 8] = a1;
            }
        }
        __syncthreads();

        unsigned Ap[2][2][4];
        #pragma unroll
        for (int mi = 0; mi < 2; mi++) {
            int r0 = mi * 16 + qr, r1 = r0 + 8;
            float m0 = wmax[r0], m1 = wmax[r1];
            #pragma unroll
            for (int ww = 1; ww < 8; ww++) {
                m0 = fmaxf(m0, wmax[ww * 32 + r0]);
                m1 = fmaxf(m1, wmax[ww * 32 + r1]);
            }
            __half2 hs0 = __floats2half2_rn(0.f, 0.f);
            __half2 hs1 = hs0;
            #pragma unroll
            for (int ki = 0; ki < 2; ki++)
                #pragma unroll
                for (int c = 0; c < 2; c++) {
                    int ni = 2 * ki + c;
                    unsigned wlo = h2ex2(packh2(Cs[mi][ni][0] - m0, Cs[mi][ni][1] - m0));
                    unsigned whi = h2ex2(packh2(Cs[mi][ni][2] - m1, Cs[mi][ni][3] - m1));
                    Ap[mi][ki][2 * c]     = wlo;
                    Ap[mi][ki][2 * c + 1] = whi;
                    hs0 = __hadd2(hs0, *(__half2*)&wlo);
                    hs1 = __hadd2(hs1, *(__half2*)&whi);
                }
            float s0 = __low2float(hs0) + __high2float(hs0);
            float s1 = __low2float(hs1) + __high2float(hs1);
            s0 += __shfl_xor_sync(0xffffffffu, s0, 1);
            s0 += __shfl_xor_sync(0xffffffffu, s0, 2);
            s1 += __shfl_xor_sync(0xffffffffu, s1, 1);
            s1 += __shfl_xor_sync(0xffffffffu, s1, 2);
            if (qc == 0) {
                wsum[w * 32 + r0] = s0;
                wsum[w * 32 + r1] = s1;
            }
        }
        __syncthreads();

        if (w == 0 && qc == 0) {
            #pragma unroll
            for (int g = 0; g < 4; g++) {
                int row = qr + g * 8;
                float s = wsum[row];
                #pragma unroll
                for (int ww = 1; ww < 8; ww++) s += wsum[ww * 32 + row];
                sinv[row] = __fdividef(1.f, s);
            }
        }

        float Co[2][2][4];
        #pragma unroll
        for (int mi = 0; mi < 2; mi++)
            #pragma unroll
            for (int ni = 0; ni < 2; ni++)
                #pragma unroll
                for (int j = 0; j < 4; j++) Co[mi][ni][j] = 0.f;
        #pragma unroll
        for (int ki = 0; ki < 2; ki++)
            #pragma unroll
            for (int ni = 0; ni < 2; ni++)
                #pragma unroll
                for (int mi = 0; mi < 2; mi++)
                    mma_f16(Co[mi][ni], Ap[mi][ki], LVh[ki][ni][0], LVh[ki][ni][1]);

        #pragma unroll
        for (int mi = 0; mi < 2; mi++)
            #pragma unroll
            for (int ni = 0; ni < 2; ni++) {
                int v = mi * 16 + qr;
                int d = ni * 8 + 2 * qc;
                float2 p01, p23;
                p01.x = Co[mi][ni][0]; p01.y = Co[mi][ni][1];
                p23.x = Co[mi][ni][2]; p23.y = Co[mi][ni][3];
                *(float2*)&pb[w * 520 + v * 16 + d] = p01;
                *(float2*)&pb[w * 520 + (v + 8) * 16 + d] = p23;
            }
        __syncthreads();

        {
            int v = tid >> 3;
            int d = (tid & 7) * 2;
            float2 s = make_float2(0.f, 0.f);
            #pragma unroll
            for (int ww = 0; ww < 8; ww++) {
                float2 p = *(float2*)&pb[ww * 520 + tid * 2];
                s.x += p.x; s.y += p.y;
            }
            float si = sinv[v];
            float2 r2 = *(const float2*)(g_r + ((size_t)((t * BB + b) * VV + v)) * FF + h * DHH + d);
            float2 res;
            res.x = r2.x * __expf(s.x * si);
            res.y = r2.y * __expf(s.y * si);
            *(float2*)(g_pre + ((size_t)(t * BB + b)) * (VV * FF)
                       + h * (VV * DHH) + v * DHH + d) = res;
        }
    }
}

// ---------------- launch ----------------
extern "C" void kernel_launch(void* const* d_in, const int* in_sizes, int n_in,
                              void* d_out, int out_size)
{
    const float* vehicles    = (const float*)d_in[0];
    const float* initial_pos = (const float*)d_in[1];
    const float* lanes       = (const float*)d_in[2];
    const unsigned char* mask_lanes = (const unsigned char*)d_in[3];
    const float* Wk = (const float*)d_in[4];
    const float* bk = (const float*)d_in[5];
    const float* Wv = (const float*)d_in[6];
    const float* bv = (const float*)d_in[7];
    const float* Wq = (const float*)d_in[8];
    const float* bq = (const float*)d_in[9];
    const float* Wr = (const float*)d_in[10];
    const float* br = (const float*)d_in[11];
    const float* Wc = (const float*)d_in[12];
    const float* bc = (const float*)d_in[13];
    float* out = (float*)d_out;

    cudaFuncSetAttribute(attn10_kernel,
                         cudaFuncAttributeMaxDynamicSharedMemorySize, CSMEM_BYTES);
    cudaFuncSetAttribute(lane_proj2_kernel,
                         cudaFuncAttributeMaxDynamicSharedMemorySize, LP_BYTES);

    float *gK, *gLV, *gq, *gr, *gpre;
    cudaGetSymbolAddress((void**)&gK,   g_Kproj);
    cudaGetSymbolAddress((void**)&gLV,  g_LV);
    cudaGetSymbolAddress((void**)&gq,   g_q);
    cudaGetSymbolAddress((void**)&gr,   g_r);
    cudaGetSymbolAddress((void**)&gpre, g_pre);

    // 1) fused lane projections + mask
    lane_proj2_kernel<<<BB * LL / 32, 256, LP_BYTES>>>(lanes, Wk, bk, Wv, bv, gK, gLV);
    mask_kernel<<<1, 256>>>(mask_lanes);

    // 2) fused q, r projections (tensor cores)
    gemm_qr_tc<<<MROWS / 64, 256>>>(vehicles, initial_pos, Wq, bq, Wr, br, gq, gr);

    // 3) attention (register-resident p, retest under clean clocks)
    attn10_kernel<<<dim3(BB * HH, TT / ATB), 256, CSMEM_BYTES>>>();

    // 4) combine + residual (tensor cores)
    gemm_c_tc<<<MROWS / 64, 256>>>(gpre, Wc, bc, out, vehicles, initial_pos);
}